// round 4
// baseline (speedup 1.0000x reference)
#include <cuda_runtime.h>
#include <math.h>
#include <cstdint>

#define BB 64
#define DIM 640
#define MK 100
#define KP 104          // padded K (zeros in 100..103), 13 k-steps of 8
#define NKS 13
#define TT 128
#define NT 5            // DIM / TT
#define NPAIR 15        // upper tile pairs
#define TRI 205120      // 640*641/2
#define EPSV 1e-5f
#define SSTR 105        // smem row stride (floats); 105 mod 32 = 9 -> <=2-way conflicts
#define TSZ (TT * SSTR) // floats per tile

// ---- scratch (static device arrays: allocation-free) ----
__device__ float g_dcov[(size_t)BB * DIM * DIM];  // upper tiles only
__device__ float g_s[BB * DIM];                   // row sums of dcov

// ---------------------------------------------------------------------------
__device__ __forceinline__ uint32_t f2tf32(float v) {
    uint32_t r;
    asm("cvt.rna.tf32.f32 %0, %1;" : "=r"(r) : "f"(v));
    return r;
}

__device__ __forceinline__ void mma8(float* c, const uint32_t* a, const uint32_t* b) {
    asm volatile(
        "mma.sync.aligned.m16n8k8.row.col.f32.tf32.tf32.f32 "
        "{%0,%1,%2,%3}, {%4,%5,%6,%7}, {%8,%9}, {%0,%1,%2,%3};"
        : "+f"(c[0]), "+f"(c[1]), "+f"(c[2]), "+f"(c[3])
        : "r"(a[0]), "r"(a[1]), "r"(a[2]), "r"(a[3]), "r"(b[0]), "r"(b[1]));
}

// ---------------------------------------------------------------------------
// Kernel 0: zero row-sum accumulators
// ---------------------------------------------------------------------------
__global__ void zero_kernel() {
    int idx = blockIdx.x * 256 + threadIdx.x;
    if (idx < BB * DIM) g_s[idx] = 0.f;
}

// ---------------------------------------------------------------------------
// Kernel 1: tf32-split Gram (mma.sync) -> dcov tile + row/col sums
// 256 threads, 1 CTA per (upper tile pair, batch)
// ---------------------------------------------------------------------------
__global__ __launch_bounds__(256, 1)
void gram_dcov_kernel(const float* __restrict__ x, const float* __restrict__ t) {
    int p = blockIdx.x, b = blockIdx.y;
    int ti = 0, rem = p;
    while (rem >= NT - ti) { rem -= NT - ti; ti++; }
    int tj = ti + rem;
    int i0 = ti * TT, j0 = tj * TT;
    bool diag = (ti == tj);

    extern __shared__ float sm[];
    float* Ah = sm;
    float* Al = Ah + TSZ;
    float* Bh = Al + TSZ;
    float* Bl = Bh + TSZ;

    __shared__ float di_s[TT], dj_s[TT], rs_s[TT], cs_s[TT];

    int tid = threadIdx.x;
    if (tid < TT) { rs_s[tid] = 0.f; cs_s[tid] = 0.f; }

    const float* xb = x + (size_t)b * DIM * MK;

    // ---- stage tiles: fp32 -> (tf32 hi, tf32 lo) into smem ----
    {
        const float* srcA = xb + (size_t)i0 * MK;
        for (int idx = tid; idx < TT * KP; idx += 256) {
            int r = idx / KP, k = idx - r * KP;
            float v = (k < MK) ? srcA[r * MK + k] : 0.f;
            float hf = __uint_as_float(f2tf32(v));
            Ah[r * SSTR + k] = hf;
            Al[r * SSTR + k] = __uint_as_float(f2tf32(v - hf));
        }
        if (!diag) {
            const float* srcB = xb + (size_t)j0 * MK;
            for (int idx = tid; idx < TT * KP; idx += 256) {
                int r = idx / KP, k = idx - r * KP;
                float v = (k < MK) ? srcB[r * MK + k] : 0.f;
                float hf = __uint_as_float(f2tf32(v));
                Bh[r * SSTR + k] = hf;
                Bl[r * SSTR + k] = __uint_as_float(f2tf32(v - hf));
            }
        }
    }
    const float* BhP = diag ? Ah : Bh;
    const float* BlP = diag ? Al : Bl;
    __syncthreads();

    // ---- row norms from the hi+lo representation (consistent with MMA) ----
    if (tid < TT) {
        float s = 0.f;
        for (int k = 0; k < KP; k++) {
            float v = Ah[tid * SSTR + k] + Al[tid * SSTR + k];
            s = fmaf(v, v, s);
        }
        di_s[tid] = s;
    } else {
        int r = tid - TT;
        float s = 0.f;
        for (int k = 0; k < KP; k++) {
            float v = BhP[r * SSTR + k] + BlP[r * SSTR + k];
            s = fmaf(v, v, s);
        }
        dj_s[r] = s;
    }

    // ---- mainloop: 3 passes (hi*hi, hi*lo, lo*hi) ----
    int wid = tid >> 5, lane = tid & 31;
    int wm = wid & 1, wn = wid >> 1;     // warp tile: 64 rows x 32 cols
    int gid = lane >> 2, tig = lane & 3;

    float acc[4][4][4];
#pragma unroll
    for (int mt = 0; mt < 4; mt++)
#pragma unroll
        for (int nt = 0; nt < 4; nt++)
#pragma unroll
            for (int q = 0; q < 4; q++) acc[mt][nt][q] = 0.f;

    const float* APs[3] = {Ah, Ah, Al};
    const float* BPs[3] = {BhP, BlP, BhP};

    for (int pass = 0; pass < 3; pass++) {
        const float* Ap = APs[pass];
        const float* Bp = BPs[pass];
        for (int ks = 0; ks < NKS; ks++) {
            int k0 = ks * 8;
            uint32_t a[4][4];
#pragma unroll
            for (int mt = 0; mt < 4; mt++) {
                int rb = wm * 64 + mt * 16;
                const float* base = Ap + (rb + gid) * SSTR + k0 + tig;
                a[mt][0] = __float_as_uint(base[0]);
                a[mt][1] = __float_as_uint(base[8 * SSTR]);
                a[mt][2] = __float_as_uint(base[4]);
                a[mt][3] = __float_as_uint(base[8 * SSTR + 4]);
            }
            uint32_t bf[4][2];
#pragma unroll
            for (int nt = 0; nt < 4; nt++) {
                int cb = wn * 32 + nt * 8;
                const float* base = Bp + (cb + gid) * SSTR + k0 + tig;
                bf[nt][0] = __float_as_uint(base[0]);
                bf[nt][1] = __float_as_uint(base[4]);
            }
#pragma unroll
            for (int mt = 0; mt < 4; mt++)
#pragma unroll
                for (int nt = 0; nt < 4; nt++)
                    mma8(acc[mt][nt], a[mt], bf[nt]);
        }
    }

    __syncthreads();  // di_s/dj_s writes + rs/cs zero-init visible

    // ---- epilogue: dcov transform, sums, store tile ----
    float et = expf(t[0]);
    float* dstb = g_dcov + ((size_t)b * DIM + i0) * DIM + j0;

#pragma unroll
    for (int mt = 0; mt < 4; mt++) {
        int rb = wm * 64 + mt * 16;
        float diA = di_s[rb + gid];
        float diB = di_s[rb + gid + 8];
        float rsumA = 0.f, rsumB = 0.f;
#pragma unroll
        for (int nt = 0; nt < 4; nt++) {
            int cb = wn * 32 + nt * 8 + tig * 2;
            float dj0 = dj_s[cb], dj1 = dj_s[cb + 1];
            float* c = acc[mt][nt];

            float q0 = fmaxf(fmaf(-2.f, c[0], diA + dj0), 0.f);
            float q1 = fmaxf(fmaf(-2.f, c[1], diA + dj1), 0.f);
            float q2 = fmaxf(fmaf(-2.f, c[2], diB + dj0), 0.f);
            float q3 = fmaxf(fmaf(-2.f, c[3], diB + dj1), 0.f);
            float v0 = sqrtf(fmaf(et, q0, EPSV));
            float v1 = sqrtf(fmaf(et, q1, EPSV));
            float v2 = sqrtf(fmaf(et, q2, EPSV));
            float v3 = sqrtf(fmaf(et, q3, EPSV));

            rsumA += v0 + v1;
            rsumB += v2 + v3;

            // column sums: reduce (v0+v2) and (v1+v3) across gid (lanes xor 4,8,16)
            float cs0 = v0 + v2, cs1 = v1 + v3;
#pragma unroll
            for (int o = 4; o <= 16; o <<= 1) {
                cs0 += __shfl_xor_sync(0xffffffffu, cs0, o);
                cs1 += __shfl_xor_sync(0xffffffffu, cs1, o);
            }
            if (gid == 0) {
                atomicAdd(&cs_s[cb], cs0);
                atomicAdd(&cs_s[cb + 1], cs1);
            }

            // store dcov
            *(float2*)(dstb + (size_t)(rb + gid) * DIM + cb)     = make_float2(v0, v1);
            *(float2*)(dstb + (size_t)(rb + gid + 8) * DIM + cb) = make_float2(v2, v3);
        }
        // row sums: reduce across tig (lanes xor 1,2)
#pragma unroll
        for (int o = 1; o <= 2; o <<= 1) {
            rsumA += __shfl_xor_sync(0xffffffffu, rsumA, o);
            rsumB += __shfl_xor_sync(0xffffffffu, rsumB, o);
        }
        if (tig == 0) {
            atomicAdd(&rs_s[rb + gid], rsumA);
            atomicAdd(&rs_s[rb + gid + 8], rsumB);
        }
    }
    __syncthreads();

    if (tid < TT) {
        atomicAdd(&g_s[b * DIM + i0 + tid], rs_s[tid]);
        if (!diag) atomicAdd(&g_s[b * DIM + j0 + tid], cs_s[tid]);
    }
}

// ---------------------------------------------------------------------------
// Kernel 2: double centering + triu extraction
// ---------------------------------------------------------------------------
__global__ __launch_bounds__(256)
void center_kernel(float* __restrict__ out) {
    int p = blockIdx.x, b = blockIdx.y;
    int ti = 0, rem = p;
    while (rem >= NT - ti) { rem -= NT - ti; ti++; }
    int tj = ti + rem;
    int i0 = ti * TT, j0 = tj * TT;
    int tid = threadIdx.x;

    __shared__ float red[256];
    const float* sb = g_s + b * DIM;
    float ss = 0.f;
    for (int i = tid; i < DIM; i += 256) ss += sb[i];
    red[tid] = ss;
    __syncthreads();
    for (int o = 128; o > 0; o >>= 1) {
        if (tid < o) red[tid] += red[tid + o];
        __syncthreads();
    }
    float gm = red[0] * (1.0f / ((float)DIM * (float)DIM));
    const float invd = 1.0f / (float)DIM;

    const float* dc = g_dcov + (size_t)b * DIM * DIM;
    float* ob = out + (size_t)b * TRI;

    for (int idx = tid; idx < TT * TT; idx += 256) {
        int li = idx >> 7, lj = idx & 127;
        int i = i0 + li, j = j0 + lj;
        if (j < i) continue;
        float v = dc[(size_t)i * DIM + j] - (sb[i] + sb[j]) * invd + gm;
        size_t base = (size_t)i * DIM - ((size_t)i * (i - 1)) / 2;
        ob[base + (j - i)] = v;
    }
}

// ---------------------------------------------------------------------------
extern "C" void kernel_launch(void* const* d_in, const int* in_sizes, int n_in,
                              void* d_out, int out_size) {
    const float* x = (const float*)d_in[0];
    const float* t = (const float*)d_in[1];
    float* out = (float*)d_out;

    const int smem1 = 4 * TSZ * (int)sizeof(float);  // 215040 B
    cudaFuncSetAttribute(gram_dcov_kernel,
                         cudaFuncAttributeMaxDynamicSharedMemorySize, smem1);

    zero_kernel<<<(BB * DIM + 255) / 256, 256>>>();
    gram_dcov_kernel<<<dim3(NPAIR, BB), 256, smem1>>>(x, t);
    center_kernel<<<dim3(NPAIR, BB), 256>>>(out);
}

// round 5
// speedup vs baseline: 1.4899x; 1.4899x over previous
#include <cuda_runtime.h>
#include <math.h>
#include <cstdint>

#define BB 64
#define DIM 640
#define MK 100
#define KP 104          // padded K, 13 k-steps of 8
#define NKS 13
#define TT 128
#define NT 5            // DIM / TT
#define NPAIR 15        // upper tile pairs
#define TRI 205120      // 640*641/2
#define EPSV 1e-5f
#define SPAD 104        // smem row stride (floats): bank stride 8 -> frag loads ~2-way max
#define TSZ (TT * SPAD)

// ---- scratch (static device arrays: allocation-free) ----
__device__ float g_dcov[(size_t)BB * DIM * DIM];   // upper tiles only
__device__ float g_sp[NT][BB][DIM];                // row-sum slots (exactly-once, no atomics)

// ---------------------------------------------------------------------------
__device__ __forceinline__ uint32_t f2tf32(float v) {
    uint32_t r;
    asm("cvt.rna.tf32.f32 %0, %1;" : "=r"(r) : "f"(v));
    return r;
}

__device__ __forceinline__ void mma8(float* c, const uint32_t* a, const uint32_t* b) {
    asm volatile(
        "mma.sync.aligned.m16n8k8.row.col.f32.tf32.tf32.f32 "
        "{%0,%1,%2,%3}, {%4,%5,%6,%7}, {%8,%9}, {%0,%1,%2,%3};"
        : "+f"(c[0]), "+f"(c[1]), "+f"(c[2]), "+f"(c[3])
        : "r"(a[0]), "r"(a[1]), "r"(a[2]), "r"(a[3]), "r"(b[0]), "r"(b[1]));
}

// ---------------------------------------------------------------------------
// Kernel 1: tf32-split Gram -> dcov tile + row/col sum slots
// 256 threads, 2 CTAs/SM, 1 CTA per (upper tile pair, batch)
// ---------------------------------------------------------------------------
__global__ __launch_bounds__(256, 2)
void gram_dcov_kernel(const float* __restrict__ x, const float* __restrict__ t) {
    int p = blockIdx.x, b = blockIdx.y;
    int ti = 0, rem = p;
    while (rem >= NT - ti) { rem -= NT - ti; ti++; }
    int tj = ti + rem;
    int i0 = ti * TT, j0 = tj * TT;
    bool diag = (ti == tj);

    extern __shared__ float sm[];
    float* A = sm;          // [128][SPAD] fp32
    float* B = A + TSZ;     // [128][SPAD] fp32 (unused when diag)

    __shared__ float di_s[TT], dj_s[TT], rs_s[TT], cs_s[TT];

    int tid = threadIdx.x;
    if (tid < TT) { rs_s[tid] = 0.f; cs_s[tid] = 0.f; }

    const float* xb = x + (size_t)b * DIM * MK;

    // ---- stage fp32 tiles (coalesced gmem, conflict-free STS) ----
    {
        const float* srcA = xb + (size_t)i0 * MK;
        for (int idx = tid; idx < TT * MK; idx += 256) {
            int r = idx / MK, m = idx - r * MK;
            A[r * SPAD + m] = srcA[idx];
        }
        for (int idx = tid; idx < TT * 4; idx += 256) {
            int r = idx >> 2;
            A[r * SPAD + MK + (idx & 3)] = 0.f;
        }
        if (!diag) {
            const float* srcB = xb + (size_t)j0 * MK;
            for (int idx = tid; idx < TT * MK; idx += 256) {
                int r = idx / MK, m = idx - r * MK;
                B[r * SPAD + m] = srcB[idx];
            }
            for (int idx = tid; idx < TT * 4; idx += 256) {
                int r = idx >> 2;
                B[r * SPAD + MK + (idx & 3)] = 0.f;
            }
        }
    }
    const float* Bp = diag ? A : B;
    __syncthreads();

    // ---- row norms (fp32), skewed k to avoid bank conflicts ----
    {
        int r = tid & 127;
        const float* src = (tid < TT) ? A : Bp;
        float s = 0.f;
        int kk = r & 103;
        for (int k = 0; k < KP; k++) {
            float v = src[r * SPAD + kk];
            s = fmaf(v, v, s);
            kk++; if (kk == KP) kk = 0;
        }
        if (tid < TT) di_s[r] = s; else dj_s[r] = s;
    }

    // ---- mainloop: register-split 3xTF32, fragments loaded once per kstep ----
    int wid = tid >> 5, lane = tid & 31;
    int wm = wid & 1, wn = wid >> 1;     // warp tile: 64 rows x 32 cols
    int gid = lane >> 2, tig = lane & 3;

    float acc[4][4][4];
#pragma unroll
    for (int mt = 0; mt < 4; mt++)
#pragma unroll
        for (int nt = 0; nt < 4; nt++)
#pragma unroll
            for (int q = 0; q < 4; q++) acc[mt][nt][q] = 0.f;

    const float* arow0 = A + (wm * 64 + gid) * SPAD + tig;
    const float* brow0 = Bp + (wn * 32 + gid) * SPAD + tig;

    for (int ks = 0; ks < NKS; ks++) {
        int k0 = ks * 8;
        // b fragments: 8 raw loads -> hi/lo
        uint32_t bhi[4][2], blo[4][2];
#pragma unroll
        for (int nt = 0; nt < 4; nt++) {
            const float* bp = brow0 + nt * 8 * SPAD + k0;
            float r0 = bp[0], r1 = bp[4];
            bhi[nt][0] = f2tf32(r0);
            bhi[nt][1] = f2tf32(r1);
            blo[nt][0] = f2tf32(r0 - __uint_as_float(bhi[nt][0]));
            blo[nt][1] = f2tf32(r1 - __uint_as_float(bhi[nt][1]));
        }
#pragma unroll
        for (int mt = 0; mt < 4; mt++) {
            const float* ap = arow0 + mt * 16 * SPAD + k0;
            float r0 = ap[0];
            float r1 = ap[8 * SPAD];
            float r2 = ap[4];
            float r3 = ap[8 * SPAD + 4];
            uint32_t ahi[4], alo[4];
            ahi[0] = f2tf32(r0); alo[0] = f2tf32(r0 - __uint_as_float(ahi[0]));
            ahi[1] = f2tf32(r1); alo[1] = f2tf32(r1 - __uint_as_float(ahi[1]));
            ahi[2] = f2tf32(r2); alo[2] = f2tf32(r2 - __uint_as_float(ahi[2]));
            ahi[3] = f2tf32(r3); alo[3] = f2tf32(r3 - __uint_as_float(ahi[3]));
#pragma unroll
            for (int nt = 0; nt < 4; nt++) {
                mma8(acc[mt][nt], ahi, bhi[nt]);
                mma8(acc[mt][nt], ahi, blo[nt]);
                mma8(acc[mt][nt], alo, bhi[nt]);
            }
        }
    }

    __syncthreads();  // di_s/dj_s + rs/cs zero-init visible

    // ---- epilogue: dcov transform, sums, store tile ----
    float et = expf(t[0]);
    float* dstb = g_dcov + ((size_t)b * DIM + i0) * DIM + j0;

#pragma unroll
    for (int mt = 0; mt < 4; mt++) {
        int rb = wm * 64 + mt * 16;
        float diA = di_s[rb + gid];
        float diB = di_s[rb + gid + 8];
        float rsumA = 0.f, rsumB = 0.f;
#pragma unroll
        for (int nt = 0; nt < 4; nt++) {
            int cb = wn * 32 + nt * 8 + tig * 2;
            float dj0 = dj_s[cb], dj1 = dj_s[cb + 1];
            float* c = acc[mt][nt];

            float q0 = fmaxf(fmaf(-2.f, c[0], diA + dj0), 0.f);
            float q1 = fmaxf(fmaf(-2.f, c[1], diA + dj1), 0.f);
            float q2 = fmaxf(fmaf(-2.f, c[2], diB + dj0), 0.f);
            float q3 = fmaxf(fmaf(-2.f, c[3], diB + dj1), 0.f);
            float v0 = sqrtf(fmaf(et, q0, EPSV));
            float v1 = sqrtf(fmaf(et, q1, EPSV));
            float v2 = sqrtf(fmaf(et, q2, EPSV));
            float v3 = sqrtf(fmaf(et, q3, EPSV));

            rsumA += v0 + v1;
            rsumB += v2 + v3;

            // column sums across gid (lanes xor 4,8,16)
            float cs0 = v0 + v2, cs1 = v1 + v3;
#pragma unroll
            for (int o = 4; o <= 16; o <<= 1) {
                cs0 += __shfl_xor_sync(0xffffffffu, cs0, o);
                cs1 += __shfl_xor_sync(0xffffffffu, cs1, o);
            }
            if (gid == 0) {
                atomicAdd(&cs_s[cb], cs0);
                atomicAdd(&cs_s[cb + 1], cs1);
            }

            *(float2*)(dstb + (size_t)(rb + gid) * DIM + cb)     = make_float2(v0, v1);
            *(float2*)(dstb + (size_t)(rb + gid + 8) * DIM + cb) = make_float2(v2, v3);
        }
        // row sums across tig (lanes xor 1,2)
#pragma unroll
        for (int o = 1; o <= 2; o <<= 1) {
            rsumA += __shfl_xor_sync(0xffffffffu, rsumA, o);
            rsumB += __shfl_xor_sync(0xffffffffu, rsumB, o);
        }
        if (tig == 0) {
            atomicAdd(&rs_s[rb + gid], rsumA);
            atomicAdd(&rs_s[rb + gid + 8], rsumB);
        }
    }
    __syncthreads();

    // exactly-once slot writes (no global atomics, no zero kernel)
    if (tid < TT) {
        g_sp[tj][b][i0 + tid] = rs_s[tid];
    } else if (!diag) {
        g_sp[ti][b][j0 + (tid - TT)] = cs_s[tid - TT];
    }
}

// ---------------------------------------------------------------------------
// Kernel 2: double centering + triu extraction
// ---------------------------------------------------------------------------
__global__ __launch_bounds__(256)
void center_kernel(float* __restrict__ out) {
    int p = blockIdx.x, b = blockIdx.y;
    int ti = 0, rem = p;
    while (rem >= NT - ti) { rem -= NT - ti; ti++; }
    int tj = ti + rem;
    int i0 = ti * TT, j0 = tj * TT;
    int tid = threadIdx.x;

    __shared__ float sb[DIM];
    __shared__ float red[256];
    float ss = 0.f;
    for (int i = tid; i < DIM; i += 256) {
        float v = g_sp[0][b][i] + g_sp[1][b][i] + g_sp[2][b][i]
                + g_sp[3][b][i] + g_sp[4][b][i];
        sb[i] = v;
        ss += v;
    }
    red[tid] = ss;
    __syncthreads();
    for (int o = 128; o > 0; o >>= 1) {
        if (tid < o) red[tid] += red[tid + o];
        __syncthreads();
    }
    float gm = red[0] * (1.0f / ((float)DIM * (float)DIM));
    const float invd = 1.0f / (float)DIM;

    const float* dc = g_dcov + (size_t)b * DIM * DIM;
    float* ob = out + (size_t)b * TRI;

    for (int idx = tid; idx < TT * TT; idx += 256) {
        int li = idx >> 7, lj = idx & 127;
        int i = i0 + li, j = j0 + lj;
        if (j < i) continue;
        float v = dc[(size_t)i * DIM + j] - (sb[i] + sb[j]) * invd + gm;
        size_t base = (size_t)i * DIM - ((size_t)i * (i - 1)) / 2;
        ob[base + (j - i)] = v;
    }
}

// ---------------------------------------------------------------------------
extern "C" void kernel_launch(void* const* d_in, const int* in_sizes, int n_in,
                              void* d_out, int out_size) {
    const float* x = (const float*)d_in[0];
    const float* t = (const float*)d_in[1];
    float* out = (float*)d_out;

    const int smem1 = 2 * TSZ * (int)sizeof(float);  // 106496 B -> 2 CTAs/SM
    cudaFuncSetAttribute(gram_dcov_kernel,
                         cudaFuncAttributeMaxDynamicSharedMemorySize, smem1);

    gram_dcov_kernel<<<dim3(NPAIR, BB), 256, smem1>>>(x, t);
    center_kernel<<<dim3(NPAIR, BB), 256>>>(out);
}

// round 6
// speedup vs baseline: 1.8593x; 1.2480x over previous
#include <cuda_runtime.h>
#include <math.h>
#include <cstdint>

#define BB 64
#define DIM 640
#define MK 100
#define NKS 13
#define TT 128
#define NT 5            // DIM / TT
#define NPAIR 15        // upper tile pairs
#define TRI 205120      // 640*641/2
#define EPSV 1e-5f
#define SPAD 104        // smem row stride (floats)
#define TSZ (TT * SPAD)
#define NROWS (BB * DIM)

// ---- scratch (static device arrays: allocation-free) ----
__device__ float g_sp[NT][BB][DIM];   // row-sum slots (exactly-once writes)
__device__ float g_d[NROWS];          // squared norms
__device__ float g_sb[NROWS];         // per-batch row sums, pre-scaled by 1/dim
__device__ float g_gm[BB];            // per-batch grand mean

// ---------------------------------------------------------------------------
__device__ __forceinline__ uint32_t f2tf32(float v) {
    uint32_t r;
    asm("cvt.rna.tf32.f32 %0, %1;" : "=r"(r) : "f"(v));
    return r;
}
__device__ __forceinline__ void mma8(float* c, const uint32_t* a, const uint32_t* b) {
    asm volatile(
        "mma.sync.aligned.m16n8k8.row.col.f32.tf32.tf32.f32 "
        "{%0,%1,%2,%3}, {%4,%5,%6,%7}, {%8,%9}, {%0,%1,%2,%3};"
        : "+f"(c[0]), "+f"(c[1]), "+f"(c[2]), "+f"(c[3])
        : "r"(a[0]), "r"(a[1]), "r"(a[2]), "r"(a[3]), "r"(b[0]), "r"(b[1]));
}

// ---------------------------------------------------------------------------
// Norms: one warp per x-row (coalesced), split over batch thirds
// ---------------------------------------------------------------------------
__global__ void norm_kernel(const float* __restrict__ x, int row0, int nrows) {
    int w = (blockIdx.x * 256 + threadIdx.x) >> 5;
    int lane = threadIdx.x & 31;
    if (w >= nrows) return;
    const float* xr = x + (size_t)(row0 + w) * MK;
    float s = 0.f;
#pragma unroll
    for (int k = lane; k < MK; k += 32) { float v = xr[k]; s = fmaf(v, v, s); }
#pragma unroll
    for (int o = 16; o >= 1; o >>= 1) s += __shfl_xor_sync(0xffffffffu, s, o);
    if (lane == 0) g_d[row0 + w] = s;
}

// ---------------------------------------------------------------------------
// Gram: tf32-split mma.sync -> dcov written DIRECTLY to out (triu layout)
// 256 threads, 2 CTAs/SM, 1 CTA per (upper tile pair, batch)
// ---------------------------------------------------------------------------
__global__ __launch_bounds__(256, 2)
void gram_dcov_kernel(const float* __restrict__ x, const float* __restrict__ t,
                      float* __restrict__ out) {
    int p = blockIdx.x, b = blockIdx.y;
    int ti = 0, rem = p;
    while (rem >= NT - ti) { rem -= NT - ti; ti++; }
    int tj = ti + rem;
    int i0 = ti * TT, j0 = tj * TT;
    bool diag = (ti == tj);

    extern __shared__ float sm[];
    float* A = sm;
    float* B = A + TSZ;

    __shared__ float di_s[TT], dj_s[TT], rs_s[TT], cs_s[TT];

    int tid = threadIdx.x;
    if (tid < TT) { rs_s[tid] = 0.f; cs_s[tid] = 0.f; }

    const float* xb = x + (size_t)b * DIM * MK;

    // stage fp32 tiles
    {
        const float* srcA = xb + (size_t)i0 * MK;
        for (int idx = tid; idx < TT * MK; idx += 256) {
            int r = idx / MK, m = idx - r * MK;
            A[r * SPAD + m] = srcA[idx];
        }
        for (int idx = tid; idx < TT * 4; idx += 256)
            A[(idx >> 2) * SPAD + MK + (idx & 3)] = 0.f;
        if (!diag) {
            const float* srcB = xb + (size_t)j0 * MK;
            for (int idx = tid; idx < TT * MK; idx += 256) {
                int r = idx / MK, m = idx - r * MK;
                B[r * SPAD + m] = srcB[idx];
            }
            for (int idx = tid; idx < TT * 4; idx += 256)
                B[(idx >> 2) * SPAD + MK + (idx & 3)] = 0.f;
        }
    }
    // preload norms (L2-hot)
    {
        const float* dbase = g_d + b * DIM;
        if (tid < TT) di_s[tid] = dbase[i0 + tid];
        else dj_s[tid - TT] = dbase[j0 + (tid - TT)];
    }
    const float* Bp = diag ? A : B;
    __syncthreads();

    // mainloop: register hi/lo tf32 split, fragments loaded once per k-step
    int wid = tid >> 5, lane = tid & 31;
    int wm = wid & 1, wn = wid >> 1;
    int gid = lane >> 2, tig = lane & 3;

    float acc[4][4][4];
#pragma unroll
    for (int mt = 0; mt < 4; mt++)
#pragma unroll
        for (int nt = 0; nt < 4; nt++)
#pragma unroll
            for (int q = 0; q < 4; q++) acc[mt][nt][q] = 0.f;

    const float* arow0 = A + (wm * 64 + gid) * SPAD + tig;
    const float* brow0 = Bp + (wn * 32 + gid) * SPAD + tig;

    for (int ks = 0; ks < NKS; ks++) {
        int k0 = ks * 8;
        uint32_t bhi[4][2], blo[4][2];
#pragma unroll
        for (int nt = 0; nt < 4; nt++) {
            const float* bp = brow0 + nt * 8 * SPAD + k0;
            float r0 = bp[0], r1 = bp[4];
            bhi[nt][0] = f2tf32(r0);
            bhi[nt][1] = f2tf32(r1);
            blo[nt][0] = f2tf32(r0 - __uint_as_float(bhi[nt][0]));
            blo[nt][1] = f2tf32(r1 - __uint_as_float(bhi[nt][1]));
        }
#pragma unroll
        for (int mt = 0; mt < 4; mt++) {
            const float* ap = arow0 + mt * 16 * SPAD + k0;
            float r0 = ap[0];
            float r1 = ap[8 * SPAD];
            float r2 = ap[4];
            float r3 = ap[8 * SPAD + 4];
            uint32_t ahi[4], alo[4];
            ahi[0] = f2tf32(r0); alo[0] = f2tf32(r0 - __uint_as_float(ahi[0]));
            ahi[1] = f2tf32(r1); alo[1] = f2tf32(r1 - __uint_as_float(ahi[1]));
            ahi[2] = f2tf32(r2); alo[2] = f2tf32(r2 - __uint_as_float(ahi[2]));
            ahi[3] = f2tf32(r3); alo[3] = f2tf32(r3 - __uint_as_float(ahi[3]));
#pragma unroll
            for (int nt = 0; nt < 4; nt++) {
                mma8(acc[mt][nt], ahi, bhi[nt]);
                mma8(acc[mt][nt], ahi, blo[nt]);
                mma8(acc[mt][nt], alo, bhi[nt]);
            }
        }
    }

    __syncthreads();

    // epilogue: transform + sums + triu-direct store
    float et = expf(t[0]);
    float* ob = out + (size_t)b * TRI;

#pragma unroll
    for (int mt = 0; mt < 4; mt++) {
        int rb = wm * 64 + mt * 16;
        int iA = i0 + rb + gid, iB = iA + 8;
        size_t offA = (size_t)iA * DIM - ((size_t)iA * (iA - 1)) / 2 - iA;
        size_t offB = (size_t)iB * DIM - ((size_t)iB * (iB - 1)) / 2 - iB;
        float diA = di_s[rb + gid];
        float diB = di_s[rb + gid + 8];
        float rsumA = 0.f, rsumB = 0.f;
#pragma unroll
        for (int nt = 0; nt < 4; nt++) {
            int cb = wn * 32 + nt * 8 + tig * 2;
            int jg = j0 + cb;
            float dj0 = dj_s[cb], dj1 = dj_s[cb + 1];
            float* c = acc[mt][nt];

            float q0 = fmaxf(fmaf(-2.f, c[0], diA + dj0), 0.f);
            float q1 = fmaxf(fmaf(-2.f, c[1], diA + dj1), 0.f);
            float q2 = fmaxf(fmaf(-2.f, c[2], diB + dj0), 0.f);
            float q3 = fmaxf(fmaf(-2.f, c[3], diB + dj1), 0.f);
            float v0 = sqrtf(fmaf(et, q0, EPSV));
            float v1 = sqrtf(fmaf(et, q1, EPSV));
            float v2 = sqrtf(fmaf(et, q2, EPSV));
            float v3 = sqrtf(fmaf(et, q3, EPSV));

            rsumA += v0 + v1;
            rsumB += v2 + v3;

            float cs0 = v0 + v2, cs1 = v1 + v3;
#pragma unroll
            for (int o = 4; o <= 16; o <<= 1) {
                cs0 += __shfl_xor_sync(0xffffffffu, cs0, o);
                cs1 += __shfl_xor_sync(0xffffffffu, cs1, o);
            }
            if (gid == 0) {
                atomicAdd(&cs_s[cb], cs0);
                atomicAdd(&cs_s[cb + 1], cs1);
            }

            if (!diag || jg >= iA)     ob[offA + jg]     = v0;
            if (!diag || jg + 1 >= iA) ob[offA + jg + 1] = v1;
            if (!diag || jg >= iB)     ob[offB + jg]     = v2;
            if (!diag || jg + 1 >= iB) ob[offB + jg + 1] = v3;
        }
#pragma unroll
        for (int o = 1; o <= 2; o <<= 1) {
            rsumA += __shfl_xor_sync(0xffffffffu, rsumA, o);
            rsumB += __shfl_xor_sync(0xffffffffu, rsumB, o);
        }
        if (tig == 0) {
            atomicAdd(&rs_s[rb + gid], rsumA);
            atomicAdd(&rs_s[rb + gid + 8], rsumB);
        }
    }
    __syncthreads();

    if (tid < TT) {
        g_sp[tj][b][i0 + tid] = rs_s[tid];
    } else if (!diag) {
        g_sp[ti][b][j0 + (tid - TT)] = cs_s[tid - TT];
    }
}

// ---------------------------------------------------------------------------
// Sums: per-batch row-sum vector (pre-scaled by 1/dim) + grand mean
// ---------------------------------------------------------------------------
__global__ __launch_bounds__(256)
void sums_kernel() {
    int b = blockIdx.x, tid = threadIdx.x;
    __shared__ float red[256];
    float part = 0.f;
    for (int i = tid; i < DIM; i += 256) {
        float v = g_sp[0][b][i] + g_sp[1][b][i] + g_sp[2][b][i]
                + g_sp[3][b][i] + g_sp[4][b][i];
        g_sb[b * DIM + i] = v * (1.0f / (float)DIM);
        part += v;
    }
    red[tid] = part;
    __syncthreads();
    for (int o = 128; o > 0; o >>= 1) {
        if (tid < o) red[tid] += red[tid + o];
        __syncthreads();
    }
    if (tid == 0) g_gm[b] = red[0] * (1.0f / ((float)DIM * (float)DIM));
}

// ---------------------------------------------------------------------------
// Center apply: in-place streaming RMW of out, one block per (row, batch)
// ---------------------------------------------------------------------------
__global__ __launch_bounds__(128)
void center_apply_kernel(float* __restrict__ out) {
    int i = blockIdx.x, b = blockIdx.y;
    const float* sb = g_sb + b * DIM;
    float corr = g_gm[b] - sb[i];
    float* ob = out + (size_t)b * TRI + ((size_t)i * DIM - ((size_t)i * (i - 1)) / 2);
    int L = DIM - i;
    int tid = threadIdx.x;

    int mis = (int)(((uintptr_t)ob >> 2) & 3);
    int head = (4 - mis) & 3;
    if (head > L) head = L;
    if (tid < head) ob[tid] = ob[tid] - sb[i + tid] + corr;

    int body = (L - head) >> 2;
    float4* vb = (float4*)(ob + head);
    for (int q = tid; q < body; q += 128) {
        float4 v = vb[q];
        int j = i + head + q * 4;
        v.x = v.x - sb[j]     + corr;
        v.y = v.y - sb[j + 1] + corr;
        v.z = v.z - sb[j + 2] + corr;
        v.w = v.w - sb[j + 3] + corr;
        vb[q] = v;
    }
    int done = head + body * 4;
    int tail = L - done;
    if (tid < tail) ob[done + tid] = ob[done + tid] - sb[i + done + tid] + corr;
}

// ---------------------------------------------------------------------------
extern "C" void kernel_launch(void* const* d_in, const int* in_sizes, int n_in,
                              void* d_out, int out_size) {
    const float* x = (const float*)d_in[0];
    const float* t = (const float*)d_in[1];
    float* out = (float*)d_out;

    const int smem1 = 2 * TSZ * (int)sizeof(float);  // 106496 B -> 2 CTAs/SM
    cudaFuncSetAttribute(gram_dcov_kernel,
                         cudaFuncAttributeMaxDynamicSharedMemorySize, smem1);

    // norms in 3 chunks (also positions gram for the ncu capture window)
    int c1 = NROWS / 3, c2 = NROWS / 3;
    int c3 = NROWS - c1 - c2;
    norm_kernel<<<(c1 * 32 + 255) / 256, 256>>>(x, 0, c1);
    norm_kernel<<<(c2 * 32 + 255) / 256, 256>>>(x, c1, c2);
    norm_kernel<<<(c3 * 32 + 255) / 256, 256>>>(x, c1 + c2, c3);
    gram_dcov_kernel<<<dim3(NPAIR, BB), 256, smem1>>>(x, t, out);
    sums_kernel<<<BB, 256>>>();
    center_apply_kernel<<<dim3(DIM, BB), 128>>>(out);
}

// round 8
// speedup vs baseline: 1.8843x; 1.0135x over previous
#include <cuda_runtime.h>
#include <math.h>
#include <cstdint>

#define BB 64
#define DIM 640
#define MK 100
#define NKS 13
#define TT 128
#define NT 5            // DIM / TT
#define NPAIR 15        // upper tile pairs
#define TRI 205120      // 640*641/2
#define EPSV 1e-5f
#define SPAD 105        // smem row stride: bank stride 9 -> conflict-free frag loads
#define TSZ (TT * SPAD)
#define NROWS (BB * DIM)

// ---- scratch (static device arrays: allocation-free) ----
__device__ float g_sp[NT][BB][DIM];   // row-sum slots (exactly-once writes)
__device__ float g_d[NROWS];          // squared norms
__device__ float g_sb[NROWS];         // per-batch row sums, pre-scaled by 1/dim
__device__ float g_gm[BB];            // per-batch grand mean

// ---------------------------------------------------------------------------
__device__ __forceinline__ uint32_t f2tf32(float v) {
    uint32_t r;
    asm("cvt.rna.tf32.f32 %0, %1;" : "=r"(r) : "f"(v));
    return r;
}
__device__ __forceinline__ void mma8(float* c, const uint32_t* a, const uint32_t* b) {
    asm volatile(
        "mma.sync.aligned.m16n8k8.row.col.f32.tf32.tf32.f32 "
        "{%0,%1,%2,%3}, {%4,%5,%6,%7}, {%8,%9}, {%0,%1,%2,%3};"
        : "+f"(c[0]), "+f"(c[1]), "+f"(c[2]), "+f"(c[3])
        : "r"(a[0]), "r"(a[1]), "r"(a[2]), "r"(a[3]), "r"(b[0]), "r"(b[1]));
}

// ---------------------------------------------------------------------------
// Norms: one warp per x-row (coalesced), split over batch thirds
// ---------------------------------------------------------------------------
__global__ void norm_kernel(const float* __restrict__ x, int row0, int nrows) {
    int w = (blockIdx.x * 256 + threadIdx.x) >> 5;
    int lane = threadIdx.x & 31;
    if (w >= nrows) return;
    const float* xr = x + (size_t)(row0 + w) * MK;
    float s = 0.f;
#pragma unroll
    for (int k = lane; k < MK; k += 32) { float v = xr[k]; s = fmaf(v, v, s); }
#pragma unroll
    for (int o = 16; o >= 1; o >>= 1) s += __shfl_xor_sync(0xffffffffu, s, o);
    if (lane == 0) g_d[row0 + w] = s;
}

// ---------------------------------------------------------------------------
// Gram: single-cvt Dekker tf32 split -> 3x mma.sync -> triu-direct store
// 256 threads, 2 CTAs/SM, 1 CTA per (upper tile pair, batch)
// ---------------------------------------------------------------------------
__global__ __launch_bounds__(256, 2)
void gram_dcov_kernel(const float* __restrict__ x, const float* __restrict__ t,
                      float* __restrict__ out) {
    int p = blockIdx.x, b = blockIdx.y;
    int ti = 0, rem = p;
    while (rem >= NT - ti) { rem -= NT - ti; ti++; }
    int tj = ti + rem;
    int i0 = ti * TT, j0 = tj * TT;
    bool diag = (ti == tj);

    extern __shared__ float sm[];
    float* A = sm;
    float* B = A + TSZ;

    __shared__ float di_s[TT], dj_s[TT], rs_s[TT], cs_s[TT];

    int tid = threadIdx.x;
    if (tid < TT) { rs_s[tid] = 0.f; cs_s[tid] = 0.f; }

    const float* xb = x + (size_t)b * DIM * MK;

    // stage fp32 tiles
    {
        const float* srcA = xb + (size_t)i0 * MK;
        for (int idx = tid; idx < TT * MK; idx += 256) {
            int r = idx / MK, m = idx - r * MK;
            A[r * SPAD + m] = srcA[idx];
        }
        for (int idx = tid; idx < TT * 4; idx += 256)
            A[(idx >> 2) * SPAD + MK + (idx & 3)] = 0.f;
        if (!diag) {
            const float* srcB = xb + (size_t)j0 * MK;
            for (int idx = tid; idx < TT * MK; idx += 256) {
                int r = idx / MK, m = idx - r * MK;
                B[r * SPAD + m] = srcB[idx];
            }
            for (int idx = tid; idx < TT * 4; idx += 256)
                B[(idx >> 2) * SPAD + MK + (idx & 3)] = 0.f;
        }
    }
    // preload norms (L2-hot)
    {
        const float* dbase = g_d + b * DIM;
        if (tid < TT) di_s[tid] = dbase[i0 + tid];
        else dj_s[tid - TT] = dbase[j0 + (tid - TT)];
    }
    const float* Bp = diag ? A : B;
    __syncthreads();

    // mainloop: hi = cvt.rna.tf32(v); lo = v - hi (exact, fed raw: HW uses top 19 bits)
    int wid = tid >> 5, lane = tid & 31;
    int wm = wid & 1, wn = wid >> 1;
    int gid = lane >> 2, tig = lane & 3;

    float acc[4][4][4];
#pragma unroll
    for (int mt = 0; mt < 4; mt++)
#pragma unroll
        for (int nt = 0; nt < 4; nt++)
#pragma unroll
            for (int q = 0; q < 4; q++) acc[mt][nt][q] = 0.f;

    const float* arow0 = A + (wm * 64 + gid) * SPAD + tig;
    const float* brow0 = Bp + (wn * 32 + gid) * SPAD + tig;

    for (int ks = 0; ks < NKS; ks++) {
        int k0 = ks * 8;
        uint32_t bhi[4][2], blo[4][2];
#pragma unroll
        for (int nt = 0; nt < 4; nt++) {
            const float* bp = brow0 + nt * 8 * SPAD + k0;
            float r0 = bp[0], r1 = bp[4];
            bhi[nt][0] = f2tf32(r0);
            bhi[nt][1] = f2tf32(r1);
            blo[nt][0] = __float_as_uint(r0 - __uint_as_float(bhi[nt][0]));
            blo[nt][1] = __float_as_uint(r1 - __uint_as_float(bhi[nt][1]));
        }
#pragma unroll
        for (int mt = 0; mt < 4; mt++) {
            const float* ap = arow0 + mt * 16 * SPAD + k0;
            float r0 = ap[0];
            float r1 = ap[8 * SPAD];
            float r2 = ap[4];
            float r3 = ap[8 * SPAD + 4];
            uint32_t ahi[4], alo[4];
            ahi[0] = f2tf32(r0); alo[0] = __float_as_uint(r0 - __uint_as_float(ahi[0]));
            ahi[1] = f2tf32(r1); alo[1] = __float_as_uint(r1 - __uint_as_float(ahi[1]));
            ahi[2] = f2tf32(r2); alo[2] = __float_as_uint(r2 - __uint_as_float(ahi[2]));
            ahi[3] = f2tf32(r3); alo[3] = __float_as_uint(r3 - __uint_as_float(ahi[3]));
#pragma unroll
            for (int nt = 0; nt < 4; nt++) {
                mma8(acc[mt][nt], ahi, bhi[nt]);
                mma8(acc[mt][nt], ahi, blo[nt]);
                mma8(acc[mt][nt], alo, bhi[nt]);
            }
        }
    }

    __syncthreads();

    // epilogue: transform + sums + triu-direct store
    float et = expf(t[0]);
    float* ob = out + (size_t)b * TRI;

#pragma unroll
    for (int mt = 0; mt < 4; mt++) {
        int rb = wm * 64 + mt * 16;
        int iA = i0 + rb + gid, iB = iA + 8;
        size_t offA = (size_t)iA * DIM - ((size_t)iA * (iA - 1)) / 2 - iA;
        size_t offB = (size_t)iB * DIM - ((size_t)iB * (iB - 1)) / 2 - iB;
        float diA = di_s[rb + gid];
        float diB = di_s[rb + gid + 8];
        float rsumA = 0.f, rsumB = 0.f;
#pragma unroll
        for (int nt = 0; nt < 4; nt++) {
            int cb = wn * 32 + nt * 8 + tig * 2;
            int jg = j0 + cb;
            float dj0 = dj_s[cb], dj1 = dj_s[cb + 1];
            float* c = acc[mt][nt];

            float q0 = fmaxf(fmaf(-2.f, c[0], diA + dj0), 0.f);
            float q1 = fmaxf(fmaf(-2.f, c[1], diA + dj1), 0.f);
            float q2 = fmaxf(fmaf(-2.f, c[2], diB + dj0), 0.f);
            float q3 = fmaxf(fmaf(-2.f, c[3], diB + dj1), 0.f);
            float v0 = sqrtf(fmaf(et, q0, EPSV));
            float v1 = sqrtf(fmaf(et, q1, EPSV));
            float v2 = sqrtf(fmaf(et, q2, EPSV));
            float v3 = sqrtf(fmaf(et, q3, EPSV));

            rsumA += v0 + v1;
            rsumB += v2 + v3;

            float cs0 = v0 + v2, cs1 = v1 + v3;
#pragma unroll
            for (int o = 4; o <= 16; o <<= 1) {
                cs0 += __shfl_xor_sync(0xffffffffu, cs0, o);
                cs1 += __shfl_xor_sync(0xffffffffu, cs1, o);
            }
            if (gid == 0) {
                atomicAdd(&cs_s[cb], cs0);
                atomicAdd(&cs_s[cb + 1], cs1);
            }

            if (!diag || jg >= iA)     ob[offA + jg]     = v0;
            if (!diag || jg + 1 >= iA) ob[offA + jg + 1] = v1;
            if (!diag || jg >= iB)     ob[offB + jg]     = v2;
            if (!diag || jg + 1 >= iB) ob[offB + jg + 1] = v3;
        }
#pragma unroll
        for (int o = 1; o <= 2; o <<= 1) {
            rsumA += __shfl_xor_sync(0xffffffffu, rsumA, o);
            rsumB += __shfl_xor_sync(0xffffffffu, rsumB, o);
        }
        if (tig == 0) {
            atomicAdd(&rs_s[rb + gid], rsumA);
            atomicAdd(&rs_s[rb + gid + 8], rsumB);
        }
    }
    __syncthreads();

    if (tid < TT) {
        g_sp[tj][b][i0 + tid] = rs_s[tid];
    } else if (!diag) {
        g_sp[ti][b][j0 + (tid - TT)] = cs_s[tid - TT];
    }
}

// ---------------------------------------------------------------------------
// Sums: per-batch row-sum vector (pre-scaled by 1/dim) + grand mean
// ---------------------------------------------------------------------------
__global__ __launch_bounds__(256)
void sums_kernel() {
    int b = blockIdx.x, tid = threadIdx.x;
    __shared__ float red[256];
    float part = 0.f;
    for (int i = tid; i < DIM; i += 256) {
        float v = g_sp[0][b][i] + g_sp[1][b][i] + g_sp[2][b][i]
                + g_sp[3][b][i] + g_sp[4][b][i];
        g_sb[b * DIM + i] = v * (1.0f / (float)DIM);
        part += v;
    }
    red[tid] = part;
    __syncthreads();
    for (int o = 128; o > 0; o >>= 1) {
        if (tid < o) red[tid] += red[tid + o];
        __syncthreads();
    }
    if (tid == 0) g_gm[b] = red[0] * (1.0f / ((float)DIM * (float)DIM));
}

// ---------------------------------------------------------------------------
// Center apply: in-place streaming RMW of out, one block per (row, batch)
// ---------------------------------------------------------------------------
__global__ __launch_bounds__(128)
void center_apply_kernel(float* __restrict__ out) {
    int i = blockIdx.x, b = blockIdx.y;
    const float* sb = g_sb + b * DIM;
    float corr = g_gm[b] - sb[i];
    float* ob = out + (size_t)b * TRI + ((size_t)i * DIM - ((size_t)i * (i - 1)) / 2);
    int L = DIM - i;
    int tid = threadIdx.x;

    int mis = (int)(((uintptr_t)ob >> 2) & 3);
    int head = (4 - mis) & 3;
    if (head > L) head = L;
    if (tid < head) ob[tid] = ob[tid] - sb[i + tid] + corr;

    int body = (L - head) >> 2;
    float4* vb = (float4*)(ob + head);
    for (int q = tid; q < body; q += 128) {
        float4 v = vb[q];
        int j = i + head + q * 4;
        v.x = v.x - sb[j]     + corr;
        v.y = v.y - sb[j + 1] + corr;
        v.z = v.z - sb[j + 2] + corr;
        v.w = v.w - sb[j + 3] + corr;
        vb[q] = v;
    }
    int done = head + body * 4;
    int tail = L - done;
    if (tid < tail) ob[done + tid] = ob[done + tid] - sb[i + done + tid] + corr;
}

// ---------------------------------------------------------------------------
extern "C" void kernel_launch(void* const* d_in, const int* in_sizes, int n_in,
                              void* d_out, int out_size) {
    const float* x = (const float*)d_in[0];
    const float* t = (const float*)d_in[1];
    float* out = (float*)d_out;

    const int smem1 = 2 * TSZ * (int)sizeof(float);  // 107520 B -> 2 CTAs/SM
    cudaFuncSetAttribute(gram_dcov_kernel,
                         cudaFuncAttributeMaxDynamicSharedMemorySize, smem1);

    int c1 = NROWS / 3, c2 = NROWS / 3;
    int c3 = NROWS - c1 - c2;
    norm_kernel<<<(c1 * 32 + 255) / 256, 256>>>(x, 0, c1);
    norm_kernel<<<(c2 * 32 + 255) / 256, 256>>>(x, c1, c2);
    norm_kernel<<<(c3 * 32 + 255) / 256, 256>>>(x, c1 + c2, c3);
    gram_dcov_kernel<<<dim3(NPAIR, BB), 256, smem1>>>(x, t, out);
    sums_kernel<<<BB, 256>>>();
    center_apply_kernel<<<dim3(DIM, BB), 128>>>(out);
}